// round 12
// baseline (speedup 1.0000x reference)
#include <cuda_runtime.h>
#include <cuda_bf16.h>
#include <math.h>

#define BB 64
#define TT 1024
#define MAXLAG 256
#define NT 256

// Cross-block scratch (device globals — no allocation allowed).
__device__ float g_C[BB * MAXLAG];   // per-(batch,lag) cross-correlation sums
__device__ float g_P[BB];            // per-batch loss
__device__ int   g_cnt[BB];          // per-batch arrival counters (self-resetting)
__device__ int   g_done = 0;         // global finalize counter (self-resetting)

#define FMA2(acc, a, e) \
    asm("fma.rn.f32x2 %0, %1, %2, %0;" : "+l"(acc) : "l"(a), "l"(e))

// Fused kernel, correlation form:
//   S[l] = (Q[L]-Q[l]) + Q[L-l] - 2*C[l],  C[l] = sum_p x_p . x_{p+l}
// grid = (64 batches, 8), 256 threads (8 warps) => 512 blocks.
// Warp w of block (b,y) owns chunk c = 8y+w: 4 CONSECUTIVE lags 4c+1..4c+4.
// Lane handles 2 consecutive positions/iter: 1 start v2.b64 + 3 end v2.b64
// (6-value window) + 8 packed dot-FMAs cover 16 point-pairs.
// Tail blocks: last of 8 blocks of batch b computes Q via a block scan and
// fits batch b; globally-last block reduces the mean.
__global__ __launch_bounds__(NT) void physics_kernel(
    const float* __restrict__ traj,
    const float* __restrict__ alpha_pred,
    const int* __restrict__ lengths,
    float* __restrict__ out)
{
    __shared__ __align__(16) float2 s[TT + 4];     // +4 pad: benign window over-read
    __shared__ float sQ[TT + 1];                   // exclusive prefix of |x|^2
    __shared__ float sh[16];
    __shared__ float wtot[8];
    __shared__ int flag_b, flag_all;

    const int b = blockIdx.x;
    const int y = blockIdx.y;

    // Stage 8KB trajectory: 2 x LDG.128 per thread.
    {
        const float4* tr4 = reinterpret_cast<const float4*>(traj) + (size_t)b * (TT / 2);
        float4* s4 = reinterpret_cast<float4*>(s);
        s4[threadIdx.x]      = tr4[threadIdx.x];
        s4[threadIdx.x + NT] = tr4[threadIdx.x + NT];
    }
    __syncthreads();

    const int L    = lengths[b];
    const int w    = threadIdx.x >> 5;
    const int lane = threadIdx.x & 31;

    // ---- correlation phase ----
    const int c    = 8 * y + w;            // chunk 0..63
    const int lag0 = 4 * c + 1;            // lags lag0..lag0+3
    int np0 = L - lag0;   if (np0 < 0) np0 = 0;
    int np3 = np0 - 3;    if (np3 < 0) np3 = 0;
    const int K = np3 >> 6;                // unguarded 64-position rounds

    const unsigned sbase = (unsigned)__cvta_generic_to_shared(s);
    const int par = lag0 & 1;              // alignment parity of the e-window
    unsigned addr_a = sbase + 16u * (unsigned)lane;
    unsigned addr_e = sbase + (((unsigned)(lag0 - par)) << 3) + 16u * (unsigned)lane;

    unsigned long long acc0 = 0, acc1 = 0, acc2 = 0, acc3 = 0;

    if (par == 0) {
        for (int t = 0; t < K; ++t) {
            unsigned long long a0, a1, e0, e1, e2, e3, e4, e5;
            asm("ld.shared.v2.b64 {%0,%1}, [%2];"    : "=l"(a0), "=l"(a1) : "r"(addr_a));
            asm("ld.shared.v2.b64 {%0,%1}, [%2];"    : "=l"(e0), "=l"(e1) : "r"(addr_e));
            asm("ld.shared.v2.b64 {%0,%1}, [%2+16];" : "=l"(e2), "=l"(e3) : "r"(addr_e));
            asm("ld.shared.v2.b64 {%0,%1}, [%2+32];" : "=l"(e4), "=l"(e5) : "r"(addr_e));
            FMA2(acc0, a0, e0); FMA2(acc0, a1, e1);
            FMA2(acc1, a0, e1); FMA2(acc1, a1, e2);
            FMA2(acc2, a0, e2); FMA2(acc2, a1, e3);
            FMA2(acc3, a0, e3); FMA2(acc3, a1, e4);
            addr_a += 512; addr_e += 512;
        }
    } else {
        for (int t = 0; t < K; ++t) {
            unsigned long long a0, a1, e0, e1, e2, e3, e4, e5;
            asm("ld.shared.v2.b64 {%0,%1}, [%2];"    : "=l"(a0), "=l"(a1) : "r"(addr_a));
            asm("ld.shared.v2.b64 {%0,%1}, [%2];"    : "=l"(e0), "=l"(e1) : "r"(addr_e));
            asm("ld.shared.v2.b64 {%0,%1}, [%2+16];" : "=l"(e2), "=l"(e3) : "r"(addr_e));
            asm("ld.shared.v2.b64 {%0,%1}, [%2+32];" : "=l"(e4), "=l"(e5) : "r"(addr_e));
            FMA2(acc0, a0, e1); FMA2(acc0, a1, e2);
            FMA2(acc1, a0, e2); FMA2(acc1, a1, e3);
            FMA2(acc2, a0, e3); FMA2(acc2, a1, e4);
            FMA2(acc3, a0, e4); FMA2(acc3, a1, e5);
            addr_a += 512; addr_e += 512;
        }
    }

    float c0 = __uint_as_float((unsigned)acc0) + __uint_as_float((unsigned)(acc0 >> 32));
    float c1 = __uint_as_float((unsigned)acc1) + __uint_as_float((unsigned)(acc1 >> 32));
    float c2 = __uint_as_float((unsigned)acc2) + __uint_as_float((unsigned)(acc2 >> 32));
    float c3 = __uint_as_float((unsigned)acc3) + __uint_as_float((unsigned)(acc3 >> 32));

    // Guarded tail: positions [64K, np0), <= 3 rounds of 32.
    for (int p = (K << 6) + lane; p < np0; p += 32) {
        const float2 a = s[p];
        {
            const float2 e = s[p + lag0];
            c0 = fmaf(a.x, e.x, c0); c0 = fmaf(a.y, e.y, c0);
        }
        if (p < np0 - 1) {
            const float2 e = s[p + lag0 + 1];
            c1 = fmaf(a.x, e.x, c1); c1 = fmaf(a.y, e.y, c1);
        }
        if (p < np0 - 2) {
            const float2 e = s[p + lag0 + 2];
            c2 = fmaf(a.x, e.x, c2); c2 = fmaf(a.y, e.y, c2);
        }
        if (p < np0 - 3) {
            const float2 e = s[p + lag0 + 3];
            c3 = fmaf(a.x, e.x, c3); c3 = fmaf(a.y, e.y, c3);
        }
    }

#pragma unroll
    for (int o = 16; o; o >>= 1) {
        c0 += __shfl_xor_sync(0xffffffffu, c0, o);
        c1 += __shfl_xor_sync(0xffffffffu, c1, o);
        c2 += __shfl_xor_sync(0xffffffffu, c2, o);
        c3 += __shfl_xor_sync(0xffffffffu, c3, o);
    }
    if (lane == 0) {
        float* dst = &g_C[b * MAXLAG + (lag0 - 1)];
        dst[0] = c0; dst[1] = c1; dst[2] = c2; dst[3] = c3;
        __threadfence();              // writer-side release (8 threads/block)
    }
    __syncthreads();

    // ---- per-batch arrival; last of the 8 blocks fits batch b ----
    if (threadIdx.x == 0) {
        const int old = atomicAdd(&g_cnt[b], 1);
        flag_b = (old == 7) ? 1 : 0;
        if (old == 7) __threadfence();            // acquire side
    }
    __syncthreads();
    if (!flag_b) return;

    // ---- exclusive prefix sum of |x|^2 over [0, TT] (block scan) ----
    {
        const int t = threadIdx.x;
        const float2 v0 = s[4 * t], v1 = s[4 * t + 1], v2 = s[4 * t + 2], v3 = s[4 * t + 3];
        const float q0 = v0.x * v0.x + v0.y * v0.y;
        const float q1 = v1.x * v1.x + v1.y * v1.y;
        const float q2 = v2.x * v2.x + v2.y * v2.y;
        const float q3 = v3.x * v3.x + v3.y * v3.y;
        const float tot = q0 + q1 + q2 + q3;

        float sc = tot;                              // warp inclusive scan
#pragma unroll
        for (int o = 1; o < 32; o <<= 1) {
            const float n = __shfl_up_sync(0xffffffffu, sc, o);
            if (lane >= o) sc += n;
        }
        if (lane == 31) wtot[w] = sc;
        __syncthreads();
        float base = sc - tot;
        for (int k = 0; k < w; ++k) base += wtot[k];

        sQ[4 * t]     = base;
        sQ[4 * t + 1] = base + q0;
        sQ[4 * t + 2] = base + q0 + q1;
        sQ[4 * t + 3] = base + q0 + q1 + q2;
        if (t == NT - 1) sQ[TT] = base + tot;
        __syncthreads();
    }

    // ---- fit: one thread per lag ----
    const float alpha = alpha_pred[b];
    const int   il  = threadIdx.x;
    const int   lag = il + 1;
    const int   np  = L - lag;
    const int   cnt = (np > 0) ? np : 1;             // counts = max(#valid, 1)
    const float C   = __ldcg(&g_C[b * MAXLAG + il]); // fresh L2 data
    float S = (sQ[L] - sQ[lag]) + sQ[(np > 0) ? np : 0] - 2.f * C;
    const float lm = logf(S / (float)cnt + 1e-8f);
    const float ll = logf((float)lag);
    const float m  = (L > lag) ? 1.f : 0.f;
    const float resid = lm - alpha * ll;

    // reduction 1: sum(resid*m), sum(m)
    float sr = resid * m, sm = m;
#pragma unroll
    for (int o = 16; o; o >>= 1) {
        sr += __shfl_xor_sync(0xffffffffu, sr, o);
        sm += __shfl_xor_sync(0xffffffffu, sm, o);
    }
    if (lane == 0) { sh[w] = sr; sh[8 + w] = sm; }
    __syncthreads();
    float srt = 0.f, smt = 0.f;
#pragma unroll
    for (int k = 0; k < 8; ++k) { srt += sh[k]; smt += sh[8 + k]; }

    const float denom     = (smt > 1.f) ? smt : 1.f;
    const float intercept = srt / denom;

    // reduction 2: sum((intercept - resid)^2 * m)
    const float dd = (intercept - resid) * m;
    float se = dd * dd;
#pragma unroll
    for (int o = 16; o; o >>= 1) se += __shfl_xor_sync(0xffffffffu, se, o);
    __syncthreads();
    if (lane == 0) sh[w] = se;
    __syncthreads();

    if (threadIdx.x == 0) {
        float t = 0.f;
#pragma unroll
        for (int k = 0; k < 8; ++k) t += sh[k];
        g_cnt[b] = 0;                       // reset for next graph replay
        g_P[b]   = t / denom;
        __threadfence();                    // publish g_P[b]
        const int old = atomicAdd(&g_done, 1);
        flag_all = (old == BB - 1) ? 1 : 0;
        if (old == BB - 1) __threadfence(); // acquire side
    }
    __syncthreads();
    if (!flag_all) return;

    // ---- globally-last block: mean over batches ----
    if (threadIdx.x < 32) {
        float t = __ldcg(&g_P[threadIdx.x]) + __ldcg(&g_P[threadIdx.x + 32]);
#pragma unroll
        for (int o = 16; o; o >>= 1) t += __shfl_xor_sync(0xffffffffu, t, o);
        if (threadIdx.x == 0) {
            out[0] = t / (float)BB;
            g_done = 0;                     // reset for next graph replay
        }
    }
}

extern "C" void kernel_launch(void* const* d_in, const int* in_sizes, int n_in,
                              void* d_out, int out_size)
{
    const float* alpha_pred = (const float*)d_in[0];
    const float* trajectory = (const float*)d_in[1];
    const int*   lengths    = (const int*)d_in[2];
    float* out = (float*)d_out;

    dim3 g1(BB, 8, 1);
    physics_kernel<<<g1, NT>>>(trajectory, alpha_pred, lengths, out);
}